// round 14
// baseline (speedup 1.0000x reference)
#include <cuda_runtime.h>
#include <cuda_fp16.h>
#include <cstdint>

#define B_ 2
#define L_ 4096
#define C_ 512
#define H_ 8
#define D_ 64
#define THREE_C 1536
#define ROWS_ (B_ * L_)
#define NROWS 65536            // B*H*L row-head pairs
#define NSPLIT 2

// fp16 hi/lo split buffers
static __device__ __half g_xhi[(size_t)ROWS_ * C_];
static __device__ __half g_xlo[(size_t)ROWS_ * C_];
static __device__ __half g_wkhi[(size_t)C_ * THREE_C];
static __device__ __half g_wklo[(size_t)C_ * THREE_C];
static __device__ __half g_wohi[(size_t)C_ * C_];
static __device__ __half g_khi[(size_t)ROWS_ * C_];
static __device__ __half g_klo[(size_t)ROWS_ * C_];
static __device__ __half g_qhi[(size_t)ROWS_ * C_];   // pre-scaled by sqrt(512)*log2(e)
static __device__ __half g_qlo[(size_t)ROWS_ * C_];
static __device__ __half g_vhi[(size_t)ROWS_ * C_];
static __device__ __half g_ahi[(size_t)ROWS_ * C_];
// split-K partials + arrival counters (self-resetting across graph replays)
static __device__ float g_po[(size_t)NSPLIT * NROWS * D_];
static __device__ float g_pm[NSPLIT * NROWS];
static __device__ float g_prs[NSPLIT * NROWS];
static __device__ int   g_ctr[512];

#define QSCALE 32.644462410f   // sqrt(512) * log2(e)

// ============================================================================
// Small PTX helpers
// ============================================================================
__device__ __forceinline__ uint32_t smem_u32(const void* p) {
    uint32_t a;
    asm("{ .reg .u64 t; cvta.to.shared.u64 t, %1; cvt.u32.u64 %0, t; }"
        : "=r"(a) : "l"(p));
    return a;
}
#define CP16(dst, src) \
    asm volatile("cp.async.cg.shared.global [%0], [%1], 16;" :: "r"(dst), "l"(src))
#define CP_COMMIT() asm volatile("cp.async.commit_group;" ::: "memory")
#define CP_WAIT(n)  asm volatile("cp.async.wait_group %0;" :: "n"(n) : "memory")

__device__ __forceinline__ uint4 ldsm4(uint32_t addr) {
    uint4 v;
    asm volatile("ldmatrix.sync.aligned.m8n8.x4.shared.b16 {%0,%1,%2,%3}, [%4];"
                 : "=r"(v.x), "=r"(v.y), "=r"(v.z), "=r"(v.w) : "r"(addr));
    return v;
}
__device__ __forceinline__ uint4 ldsm4t(uint32_t addr) {
    uint4 v;
    asm volatile("ldmatrix.sync.aligned.m8n8.x4.trans.shared.b16 {%0,%1,%2,%3}, [%4];"
                 : "=r"(v.x), "=r"(v.y), "=r"(v.z), "=r"(v.w) : "r"(addr));
    return v;
}
__device__ __forceinline__ void mma16816(float* c, uint32_t a0, uint32_t a1,
                                         uint32_t a2, uint32_t a3,
                                         uint32_t b0, uint32_t b1) {
    asm volatile(
        "mma.sync.aligned.m16n8k16.row.col.f32.f16.f16.f32 "
        "{%0,%1,%2,%3}, {%4,%5,%6,%7}, {%8,%9}, {%0,%1,%2,%3};"
        : "+f"(c[0]), "+f"(c[1]), "+f"(c[2]), "+f"(c[3])
        : "r"(a0), "r"(a1), "r"(a2), "r"(a3), "r"(b0), "r"(b1));
}

// MUFU-free exp2 (deg-4)
__device__ __forceinline__ float exp2_fast(float d) {
    d = fmaxf(d, -80.f);
    float t = d + 12582912.f;
    float f = d - (t - 12582912.f);
    float p = 9.61812911e-3f;
    p = fmaf(p, f, 5.55041087e-2f);
    p = fmaf(p, f, 2.40226507e-1f);
    p = fmaf(p, f, 6.93147181e-1f);
    p = fmaf(p, f, 1.0f);
    return __int_as_float(__float_as_int(p) +
                          (int)((uint32_t)__float_as_int(t) << 23));
}

// ============================================================================
// Fused fp32 -> fp16 hi/lo split (one launch, 1536 blocks).
// ============================================================================
__global__ void __launch_bounds__(256) split_all(
    const float4* __restrict__ x, const float4* __restrict__ wk,
    const float4* __restrict__ wo)
{
    const float4* src;
    uint2 *hi, *lo;
    int n4, bid0, nblk;
    if (blockIdx.x < 1024) {
        src = x; hi = (uint2*)g_xhi; lo = (uint2*)g_xlo;
        n4 = ROWS_ * C_ / 4; bid0 = 0; nblk = 1024;
    } else if (blockIdx.x < 1408) {
        src = wk; hi = (uint2*)g_wkhi; lo = (uint2*)g_wklo;
        n4 = C_ * THREE_C / 4; bid0 = 1024; nblk = 384;
    } else {
        src = wo; hi = (uint2*)g_wohi; lo = nullptr;
        n4 = C_ * C_ / 4; bid0 = 1408; nblk = 128;
    }
    for (int i = (blockIdx.x - bid0) * blockDim.x + threadIdx.x; i < n4;
         i += nblk * blockDim.x) {
        float4 v = src[i];
        __half2 h0 = __floats2half2_rn(v.x, v.y);
        __half2 h1 = __floats2half2_rn(v.z, v.w);
        hi[i] = make_uint2(*(uint32_t*)&h0, *(uint32_t*)&h1);
        if (lo) {
            float2 f0 = __half22float2(h0), f1 = __half22float2(h1);
            __half2 l0 = __floats2half2_rn(v.x - f0.x, v.y - f0.y);
            __half2 l1 = __floats2half2_rn(v.z - f1.x, v.w - f1.y);
            lo[i] = make_uint2(*(uint32_t*)&l0, *(uint32_t*)&l1);
        }
    }
}

// ============================================================================
// HMMA GEMM: 256 thr, BM=128, BN=64, BK=64.
// MODE 1: k/q chunks, 3 chains (unrolled), full hi+lo smem.
// MODE 2: v chunk, 1 chain, compact smem. MODE 0: out-proj, 1 chain, compact.
// ============================================================================
#define RSTR 144

template <int MODE>
__global__ void __launch_bounds__(256) hgemm(
    const __half* __restrict__ Ahi, const __half* __restrict__ Alo,
    const __half* __restrict__ Bhi, const __half* __restrict__ Blo,
    const float* __restrict__ bias, float* __restrict__ out, int N)
{
    constexpr bool CORR = (MODE == 1);
    constexpr int NCHAIN = CORR ? 3 : 1;
    constexpr int SA_HI = 0;
    constexpr int SA_LO = CORR ? 128 * RSTR : 0;
    constexpr int SB_HI = CORR ? 2 * 128 * RSTR : 128 * RSTR;
    constexpr int SB_LO = CORR ? 2 * 128 * RSTR + 64 * RSTR : 0;
    constexpr int STGSZ = CORR ? (2 * 128 * RSTR + 2 * 64 * RSTR) : 192 * RSTR;

    extern __shared__ char smem[];
    const uint32_t sb = smem_u32(smem);
    const int tid = threadIdx.x;
    const int lane = tid & 31;
    const int wid = tid >> 5;
    const int bm = blockIdx.y * 128;
    const int bn = blockIdx.x * 64;
    const int chunk = (MODE == 1) ? (bn >> 9) : 0;      // MODE1: 0=k 1=q

    auto issue_stage = [&](int stage, int k0) {
        const uint32_t stg = sb + stage * STGSZ;
#pragma unroll
        for (int k = 0; k < 4; ++k) {
            int idx = tid + k * 256;
            int r = idx >> 3, c = idx & 7;
            CP16(stg + SA_HI + r * RSTR + c * 16,
                 Ahi + (size_t)(bm + r) * C_ + k0 + c * 8);
            if (CORR)
                CP16(stg + SA_LO + r * RSTR + c * 16,
                     Alo + (size_t)(bm + r) * C_ + k0 + c * 8);
        }
#pragma unroll
        for (int k = 0; k < 2; ++k) {
            int idx = tid + k * 256;
            int r = idx >> 3, c = idx & 7;
            CP16(stg + SB_HI + r * RSTR + c * 16,
                 Bhi + (size_t)(k0 + r) * N + bn + c * 8);
            if (CORR)
                CP16(stg + SB_LO + r * RSTR + c * 16,
                     Blo + (size_t)(k0 + r) * N + bn + c * 8);
        }
    };
    issue_stage(0, 0);
    CP_COMMIT();

    float acc[8][4];
#pragma unroll
    for (int nb = 0; nb < 8; ++nb)
#pragma unroll
        for (int j = 0; j < 4; ++j) acc[nb][j] = 0.f;

    const int qr0 = wid * 16;
    const uint32_t a_row_off =
        (uint32_t)((qr0 + (lane & 7) + ((lane >> 3) & 1) * 8) * RSTR + (lane >> 4) * 16);

    for (int kt = 0; kt < 8; ++kt) {
        if (kt + 1 < 8) {
            issue_stage((kt + 1) & 1, (kt + 1) * 64);
            CP_COMMIT();
            CP_WAIT(1);
        } else {
            CP_WAIT(0);
        }
        __syncthreads();

        const uint32_t stg = sb + (kt & 1) * STGSZ;
#pragma unroll
        for (int chain = 0; chain < NCHAIN; ++chain) {
            const uint32_t abase = stg + (chain == 2 ? SA_LO : SA_HI) + a_row_off;
            const uint32_t bbase = stg + (chain == 1 ? SB_LO : SB_HI) + lane * RSTR;
            uint4 af[4];
#pragma unroll
            for (int kb = 0; kb < 4; ++kb)
                af[kb] = ldsm4(abase + kb * 32);
#pragma unroll
            for (int nb = 0; nb < 8; ++nb) {
#pragma unroll
                for (int kbp = 0; kbp < 2; ++kbp) {
                    uint4 bb = ldsm4t(bbase + kbp * 32 * RSTR + nb * 16);
                    mma16816(acc[nb], af[2 * kbp].x, af[2 * kbp].y,
                             af[2 * kbp].z, af[2 * kbp].w, bb.x, bb.y);
                    mma16816(acc[nb], af[2 * kbp + 1].x, af[2 * kbp + 1].y,
                             af[2 * kbp + 1].z, af[2 * kbp + 1].w, bb.z, bb.w);
                }
            }
        }
        __syncthreads();
    }

    const int row0 = bm + qr0 + (lane >> 2);
    if (MODE == 0) {
#pragma unroll
        for (int nb = 0; nb < 8; ++nb) {
            int col = bn + nb * 8 + 2 * (lane & 3);
            float2 b2 = *(const float2*)(bias + col);
            *(float2*)(out + (size_t)row0 * C_ + col) =
                make_float2(acc[nb][0] + b2.x, acc[nb][1] + b2.y);
            *(float2*)(out + (size_t)(row0 + 8) * C_ + col) =
                make_float2(acc[nb][2] + b2.x, acc[nb][3] + b2.y);
        }
    } else if (MODE == 2) {
#pragma unroll
        for (int nb = 0; nb < 8; ++nb) {
            int lc = bn + nb * 8 + 2 * (lane & 3);
#pragma unroll
            for (int half_ : {0, 1}) {
                int row = row0 + half_ * 8;
                __half2 h = __floats2half2_rn(acc[nb][2 * half_],
                                              acc[nb][2 * half_ + 1]);
                *(uint32_t*)(g_vhi + (size_t)row * C_ + lc) = *(uint32_t*)&h;
            }
        }
    } else {
        __half* hiB = chunk ? g_qhi : g_khi;
        __half* loB = chunk ? g_qlo : g_klo;
        const float sc = chunk ? QSCALE : 1.f;
#pragma unroll
        for (int nb = 0; nb < 8; ++nb) {
            int lc = (bn & 511) + nb * 8 + 2 * (lane & 3);
#pragma unroll
            for (int half_ : {0, 1}) {
                int row = row0 + half_ * 8;
                float v0 = acc[nb][2 * half_] * sc;
                float v1 = acc[nb][2 * half_ + 1] * sc;
                __half2 h = __floats2half2_rn(v0, v1);
                float2 hf = __half22float2(h);
                __half2 l = __floats2half2_rn(v0 - hf.x, v1 - hf.y);
                *(uint32_t*)(hiB + (size_t)row * C_ + lc) = *(uint32_t*)&h;
                *(uint32_t*)(loB + (size_t)row * C_ + lc) = *(uint32_t*)&l;
            }
        }
    }
}

#define G_SMEM_FULL (2 * (2 * 128 * RSTR + 2 * 64 * RSTR))   // 110592
#define G_SMEM_CPT  (2 * (192 * RSTR))                        // 55296

// ============================================================================
// Attention, split-K + fused last-arriver combine.
// ============================================================================
#define QHI_OFF 0
#define QLO_OFF (128 * RSTR)
#define STG_OFF (2 * 128 * RSTR)
#define TSZ (64 * RSTR)
#define KHI_SUB 0
#define KLO_SUB TSZ
#define VHI_SUB (2 * TSZ)
#define STG_SZ (3 * TSZ)                   // 27648
#define ATTN_SMEM (STG_OFF + 2 * STG_SZ)   // 92160 B

__global__ void __launch_bounds__(256) attn_mma()
{
    extern __shared__ char smem[];
    const uint32_t sb = smem_u32(smem);
    const int tid = threadIdx.x;
    const int lane = tid & 31;
    const int wid = tid >> 5;

    const int split = blockIdx.x & 1;
    const int qt = (blockIdx.x >> 1) & 31;
    const int h = (blockIdx.x >> 6) & 7;
    const int b = blockIdx.x >> 9;

    const size_t bL = (size_t)b * L_;
    const int hc = h * D_;
    const int kt0 = split * 32, kt1 = kt0 + 32;

    {
        const __half* qs[2] = {g_qhi, g_qlo};
#pragma unroll
        for (int k = 0; k < 8; ++k) {
            int idx = tid + k * 256;
            int buf = idx >> 10;
            int r = (idx >> 3) & 127;
            int c = idx & 7;
            const __half* src = qs[buf] + (bL + qt * 128 + r) * C_ + hc + c * 8;
            CP16(sb + (buf ? QLO_OFF : QHI_OFF) + r * RSTR + c * 16, src);
        }
    }
    const __half* kvsrc[3] = {g_khi, g_klo, g_vhi};
    auto issue_stage = [&](int stage, int kt) {
        const uint32_t stg = sb + STG_OFF + stage * STG_SZ;
#pragma unroll
        for (int s = 0; s < 3; ++s) {
#pragma unroll
            for (int k = 0; k < 2; ++k) {
                int idx = tid + k * 256;
                int r = idx >> 3;
                int c = idx & 7;
                const __half* src = kvsrc[s] + (bL + kt * 64 + r) * C_ + hc + c * 8;
                CP16(stg + s * TSZ + r * RSTR + c * 16, src);
            }
        }
    };
    issue_stage(kt0 & 1, kt0);
    CP_COMMIT();

    float Oc[8][4];
#pragma unroll
    for (int nb = 0; nb < 8; ++nb)
#pragma unroll
        for (int j = 0; j < 4; ++j) Oc[nb][j] = 0.f;
    float m0 = -1e30f, m1 = -1e30f, rs0 = 0.f, rs1 = 0.f;

    const int qr0 = wid * 16;
    const uint32_t q_row_off =
        (uint32_t)((qr0 + (lane & 7) + ((lane >> 3) & 1) * 8) * RSTR + (lane >> 4) * 16);

    for (int kt = kt0; kt < kt1; ++kt) {
        if (kt + 1 < kt1) {
            issue_stage((kt + 1) & 1, kt + 1);
            CP_COMMIT();
            CP_WAIT(1);
        } else {
            CP_WAIT(0);
        }
        __syncthreads();

        const uint32_t stg = sb + STG_OFF + (kt & 1) * STG_SZ;

        float Sc[8][4];
#pragma unroll
        for (int nb = 0; nb < 8; ++nb)
#pragma unroll
            for (int j = 0; j < 4; ++j) Sc[nb][j] = 0.f;

#pragma unroll
        for (int chain = 0; chain < 3; ++chain) {
            const uint32_t qbase = sb + (chain == 2 ? QLO_OFF : QHI_OFF) + q_row_off;
            const uint32_t kbase = stg + (chain == 1 ? KLO_SUB : KHI_SUB);
            uint4 qf[4];
#pragma unroll
            for (int kb = 0; kb < 4; ++kb)
                qf[kb] = ldsm4(qbase + kb * 32);
            const uint32_t krow = kbase + (uint32_t)((lane & 7) * RSTR + (lane >> 3) * 16);
#pragma unroll
            for (int nb = 0; nb < 8; ++nb) {
                const uint32_t ka = krow + nb * 8 * RSTR;
#pragma unroll
                for (int kbp = 0; kbp < 2; ++kbp) {
                    uint4 bb = ldsm4(ka + kbp * 64);
                    mma16816(Sc[nb], qf[2 * kbp].x, qf[2 * kbp].y,
                             qf[2 * kbp].z, qf[2 * kbp].w, bb.x, bb.y);
                    mma16816(Sc[nb], qf[2 * kbp + 1].x, qf[2 * kbp + 1].y,
                             qf[2 * kbp + 1].z, qf[2 * kbp + 1].w, bb.z, bb.w);
                }
            }
        }

        float t0 = -1e30f, t1 = -1e30f;
#pragma unroll
        for (int nb = 0; nb < 8; ++nb) {
            t0 = fmaxf(t0, fmaxf(Sc[nb][0], Sc[nb][1]));
            t1 = fmaxf(t1, fmaxf(Sc[nb][2], Sc[nb][3]));
        }
        t0 = fmaxf(t0, __shfl_xor_sync(0xFFFFFFFFu, t0, 1));
        t0 = fmaxf(t0, __shfl_xor_sync(0xFFFFFFFFu, t0, 2));
        t1 = fmaxf(t1, __shfl_xor_sync(0xFFFFFFFFu, t1, 1));
        t1 = fmaxf(t1, __shfl_xor_sync(0xFFFFFFFFu, t1, 2));
        const float mn0 = fmaxf(m0, t0), mn1 = fmaxf(m1, t1);
        const float corr0 = exp2_fast(m0 - mn0), corr1 = exp2_fast(m1 - mn1);
        m0 = mn0; m1 = mn1;

        uint32_t pA[4][4];
        float ps0 = 0.f, ps1 = 0.f;
#pragma unroll
        for (int nb = 0; nb < 8; ++nb) {
            float p00 = exp2_fast(Sc[nb][0] - m0);
            float p01 = exp2_fast(Sc[nb][1] - m0);
            float p10 = exp2_fast(Sc[nb][2] - m1);
            float p11 = exp2_fast(Sc[nb][3] - m1);
            __half2 hlo = __floats2half2_rn(p00, p01);
            __half2 hhi = __floats2half2_rn(p10, p11);
            float2 flo = __half22float2(hlo);
            float2 fhi = __half22float2(hhi);
            ps0 += flo.x + flo.y;
            ps1 += fhi.x + fhi.y;
            uint32_t lo2 = *reinterpret_cast<uint32_t*>(&hlo);
            uint32_t hi2 = *reinterpret_cast<uint32_t*>(&hhi);
            if (nb & 1) { pA[nb >> 1][2] = lo2; pA[nb >> 1][3] = hi2; }
            else        { pA[nb >> 1][0] = lo2; pA[nb >> 1][1] = hi2; }
        }
        ps0 += __shfl_xor_sync(0xFFFFFFFFu, ps0, 1);
        ps0 += __shfl_xor_sync(0xFFFFFFFFu, ps0, 2);
        ps1 += __shfl_xor_sync(0xFFFFFFFFu, ps1, 1);
        ps1 += __shfl_xor_sync(0xFFFFFFFFu, ps1, 2);
        rs0 = rs0 * corr0 + ps0;
        rs1 = rs1 * corr1 + ps1;
#pragma unroll
        for (int nb = 0; nb < 8; ++nb) {
            Oc[nb][0] *= corr0; Oc[nb][1] *= corr0;
            Oc[nb][2] *= corr1; Oc[nb][3] *= corr1;
        }

        // O += P Vhi
        {
            const uint32_t vbase = stg + VHI_SUB + lane * RSTR;
#pragma unroll
            for (int nb = 0; nb < 8; ++nb) {
#pragma unroll
                for (int kbp = 0; kbp < 2; ++kbp) {
                    uint4 vv = ldsm4t(vbase + kbp * 32 * RSTR + nb * 16);
                    mma16816(Oc[nb], pA[2 * kbp][0], pA[2 * kbp][1],
                             pA[2 * kbp][2], pA[2 * kbp][3], vv.x, vv.y);
                    mma16816(Oc[nb], pA[2 * kbp + 1][0], pA[2 * kbp + 1][1],
                             pA[2 * kbp + 1][2], pA[2 * kbp + 1][3], vv.z, vv.w);
                }
            }
        }
        __syncthreads();
    }

    // ---------- store unnormalized partials ----------
    const int rowb = (b * H_ + h) * L_ + qt * 128 + qr0 + (lane >> 2);
    float* po = g_po + (size_t)split * NROWS * D_;
#pragma unroll
    for (int nb = 0; nb < 8; ++nb) {
        int c = nb * 8 + 2 * (lane & 3);
        *(float2*)(po + (size_t)rowb * D_ + c) = make_float2(Oc[nb][0], Oc[nb][1]);
        *(float2*)(po + (size_t)(rowb + 8) * D_ + c) = make_float2(Oc[nb][2], Oc[nb][3]);
    }
    if ((lane & 3) == 0) {
        g_pm[split * NROWS + rowb] = m0;
        g_prs[split * NROWS + rowb] = rs0;
        g_pm[split * NROWS + rowb + 8] = m1;
        g_prs[split * NROWS + rowb + 8] = rs1;
    }

    // ---------- fused combine: last arriver merges both splits ----------
    __threadfence();
    __syncthreads();
    const int blk = (b * H_ + h) * 32 + qt;
    if (tid == 0) {
        int old = atomicAdd(&g_ctr[blk], 1);
        *(int*)smem = (old == 1);
    }
    __syncthreads();
    if (*(int*)smem) {
        __threadfence();   // acquire: make other split's stores visible
        const int rbase = (b * H_ + h) * L_ + qt * 128;
        const int r = tid >> 1;                 // 0..127
        const int c0 = (tid & 1) * 32;
        const int row = rbase + r;
        const float pm0 = g_pm[row], pm1 = g_pm[NROWS + row];
        const float pr0 = g_prs[row], pr1 = g_prs[NROWS + row];
        const float mm = fmaxf(pm0, pm1);
        float a0 = exp2_fast(pm0 - mm), a1 = exp2_fast(pm1 - mm);
        const float inv = 1.f / (a0 * pr0 + a1 * pr1);
        a0 *= inv; a1 *= inv;
        const size_t obase = (bL + qt * 128 + r) * C_ + hc + c0;
        const float* p0 = g_po + (size_t)row * D_ + c0;
        const float* p1 = g_po + (size_t)NROWS * D_ + (size_t)row * D_ + c0;
#pragma unroll
        for (int i = 0; i < 8; ++i) {
            float4 v0 = *(const float4*)(p0 + i * 4);
            float4 v1 = *(const float4*)(p1 + i * 4);
            __half2 h01 = __floats2half2_rn(a0 * v0.x + a1 * v1.x,
                                            a0 * v0.y + a1 * v1.y);
            __half2 h23 = __floats2half2_rn(a0 * v0.z + a1 * v1.z,
                                            a0 * v0.w + a1 * v1.w);
            *(uint2*)(g_ahi + obase + i * 4) =
                make_uint2(*(uint32_t*)&h01, *(uint32_t*)&h23);
        }
        if (tid == 0) g_ctr[blk] = 0;   // self-reset for next graph replay
    }
}

// ============================================================================
// Launch
// ============================================================================
extern "C" void kernel_launch(void* const* d_in, const int* in_sizes, int n_in,
                              void* d_out, int out_size)
{
    const float* x     = (const float*)d_in[0];
    const float* w_kqv = (const float*)d_in[1];
    const float* w_out = (const float*)d_in[2];
    const float* b_out = (const float*)d_in[3];
    float* out = (float*)d_out;

    __half *xhi, *xlo, *wkhi, *wklo, *wohi, *ahi;
    cudaGetSymbolAddress((void**)&xhi, g_xhi);
    cudaGetSymbolAddress((void**)&xlo, g_xlo);
    cudaGetSymbolAddress((void**)&wkhi, g_wkhi);
    cudaGetSymbolAddress((void**)&wklo, g_wklo);
    cudaGetSymbolAddress((void**)&wohi, g_wohi);
    cudaGetSymbolAddress((void**)&ahi, g_ahi);

    cudaFuncSetAttribute(attn_mma,
                         cudaFuncAttributeMaxDynamicSharedMemorySize, ATTN_SMEM);
    cudaFuncSetAttribute(hgemm<0>,
                         cudaFuncAttributeMaxDynamicSharedMemorySize, G_SMEM_CPT);
    cudaFuncSetAttribute(hgemm<1>,
                         cudaFuncAttributeMaxDynamicSharedMemorySize, G_SMEM_FULL);
    cudaFuncSetAttribute(hgemm<2>,
                         cudaFuncAttributeMaxDynamicSharedMemorySize, G_SMEM_CPT);

    // 0) fused fp32 -> fp16 hi/lo splits
    split_all<<<1536, 256>>>((const float4*)x, (const float4*)w_kqv,
                             (const float4*)w_out);

    // 1a) k/q projection (3 chains, unrolled)
    hgemm<1><<<dim3(16, ROWS_ / 128), 256, G_SMEM_FULL>>>(
        xhi, xlo, wkhi, wklo, nullptr, nullptr, THREE_C);

    // 1b) v projection (1 chain, compact smem)
    hgemm<2><<<dim3(8, ROWS_ / 128), 256, G_SMEM_CPT>>>(
        xhi, nullptr, wkhi + 1024, nullptr, nullptr, nullptr, THREE_C);

    // 2) attention split-K + fused combine (grid 1024) -> g_ahi
    attn_mma<<<B_ * H_ * (L_ / 128) * NSPLIT, 256, ATTN_SMEM>>>();

    // 3) out = attn @ w_out + bias (single-chain HMMA, compact smem)
    hgemm<0><<<dim3(C_ / 64, ROWS_ / 128), 256, G_SMEM_CPT>>>(
        ahi, nullptr, wohi, nullptr, b_out, out, C_);
}

// round 15
// speedup vs baseline: 1.0453x; 1.0453x over previous
#include <cuda_runtime.h>
#include <cuda_fp16.h>
#include <cstdint>

#define B_ 2
#define L_ 4096
#define C_ 512
#define H_ 8
#define D_ 64
#define THREE_C 1536
#define ROWS_ (B_ * L_)
#define NROWS 65536            // B*H*L row-head pairs
#define NSPLIT 2

// fp16 hi/lo split buffers
static __device__ __half g_xhi[(size_t)ROWS_ * C_];
static __device__ __half g_xlo[(size_t)ROWS_ * C_];
static __device__ __half g_wkhi[(size_t)C_ * THREE_C];
static __device__ __half g_wklo[(size_t)C_ * THREE_C];
static __device__ __half g_wohi[(size_t)C_ * C_];
static __device__ __half g_khi[(size_t)ROWS_ * C_];
static __device__ __half g_klo[(size_t)ROWS_ * C_];
static __device__ __half g_qhi[(size_t)ROWS_ * C_];   // pre-scaled by sqrt(512)*log2(e)
static __device__ __half g_qlo[(size_t)ROWS_ * C_];
static __device__ __half g_vhi[(size_t)ROWS_ * C_];
static __device__ __half g_ahi[(size_t)ROWS_ * C_];
// split-K partials
static __device__ float g_po[(size_t)NSPLIT * NROWS * D_];
static __device__ float g_pm[NSPLIT * NROWS];
static __device__ float g_prs[NSPLIT * NROWS];

#define QSCALE 32.644462410f   // sqrt(512) * log2(e)

// ============================================================================
// Small PTX helpers
// ============================================================================
__device__ __forceinline__ uint32_t smem_u32(const void* p) {
    uint32_t a;
    asm("{ .reg .u64 t; cvta.to.shared.u64 t, %1; cvt.u32.u64 %0, t; }"
        : "=r"(a) : "l"(p));
    return a;
}
#define CP16(dst, src) \
    asm volatile("cp.async.cg.shared.global [%0], [%1], 16;" :: "r"(dst), "l"(src))
#define CP_COMMIT() asm volatile("cp.async.commit_group;" ::: "memory")
#define CP_WAIT(n)  asm volatile("cp.async.wait_group %0;" :: "n"(n) : "memory")

__device__ __forceinline__ uint4 ldsm4(uint32_t addr) {
    uint4 v;
    asm volatile("ldmatrix.sync.aligned.m8n8.x4.shared.b16 {%0,%1,%2,%3}, [%4];"
                 : "=r"(v.x), "=r"(v.y), "=r"(v.z), "=r"(v.w) : "r"(addr));
    return v;
}
__device__ __forceinline__ uint4 ldsm4t(uint32_t addr) {
    uint4 v;
    asm volatile("ldmatrix.sync.aligned.m8n8.x4.trans.shared.b16 {%0,%1,%2,%3}, [%4];"
                 : "=r"(v.x), "=r"(v.y), "=r"(v.z), "=r"(v.w) : "r"(addr));
    return v;
}
__device__ __forceinline__ void mma16816(float* c, uint32_t a0, uint32_t a1,
                                         uint32_t a2, uint32_t a3,
                                         uint32_t b0, uint32_t b1) {
    asm volatile(
        "mma.sync.aligned.m16n8k16.row.col.f32.f16.f16.f32 "
        "{%0,%1,%2,%3}, {%4,%5,%6,%7}, {%8,%9}, {%0,%1,%2,%3};"
        : "+f"(c[0]), "+f"(c[1]), "+f"(c[2]), "+f"(c[3])
        : "r"(a0), "r"(a1), "r"(a2), "r"(a3), "r"(b0), "r"(b1));
}

// MUFU-free exp2 (deg-4)
__device__ __forceinline__ float exp2_fast(float d) {
    d = fmaxf(d, -80.f);
    float t = d + 12582912.f;
    float f = d - (t - 12582912.f);
    float p = 9.61812911e-3f;
    p = fmaf(p, f, 5.55041087e-2f);
    p = fmaf(p, f, 2.40226507e-1f);
    p = fmaf(p, f, 6.93147181e-1f);
    p = fmaf(p, f, 1.0f);
    return __int_as_float(__float_as_int(p) +
                          (int)((uint32_t)__float_as_int(t) << 23));
}

// ============================================================================
// Fused fp32 -> fp16 hi/lo split (one launch, 1536 blocks).
// ============================================================================
__global__ void __launch_bounds__(256) split_all(
    const float4* __restrict__ x, const float4* __restrict__ wk,
    const float4* __restrict__ wo)
{
    const float4* src;
    uint2 *hi, *lo;
    int n4, bid0, nblk;
    if (blockIdx.x < 1024) {
        src = x; hi = (uint2*)g_xhi; lo = (uint2*)g_xlo;
        n4 = ROWS_ * C_ / 4; bid0 = 0; nblk = 1024;
    } else if (blockIdx.x < 1408) {
        src = wk; hi = (uint2*)g_wkhi; lo = (uint2*)g_wklo;
        n4 = C_ * THREE_C / 4; bid0 = 1024; nblk = 384;
    } else {
        src = wo; hi = (uint2*)g_wohi; lo = nullptr;
        n4 = C_ * C_ / 4; bid0 = 1408; nblk = 128;
    }
    for (int i = (blockIdx.x - bid0) * blockDim.x + threadIdx.x; i < n4;
         i += nblk * blockDim.x) {
        float4 v = src[i];
        __half2 h0 = __floats2half2_rn(v.x, v.y);
        __half2 h1 = __floats2half2_rn(v.z, v.w);
        hi[i] = make_uint2(*(uint32_t*)&h0, *(uint32_t*)&h1);
        if (lo) {
            float2 f0 = __half22float2(h0), f1 = __half22float2(h1);
            __half2 l0 = __floats2half2_rn(v.x - f0.x, v.y - f0.y);
            __half2 l1 = __floats2half2_rn(v.z - f1.x, v.w - f1.y);
            lo[i] = make_uint2(*(uint32_t*)&l0, *(uint32_t*)&l1);
        }
    }
}

// ============================================================================
// HMMA GEMM: 256 thr, BM=128, BN=64, BK=64.
// MODE 1: k/q chunks, 3 chains (unrolled), full hi+lo smem.
// MODE 2: v chunk, 1 chain, compact smem. MODE 0: out-proj, 1 chain, compact.
// ============================================================================
#define RSTR 144

template <int MODE>
__global__ void __launch_bounds__(256) hgemm(
    const __half* __restrict__ Ahi, const __half* __restrict__ Alo,
    const __half* __restrict__ Bhi, const __half* __restrict__ Blo,
    const float* __restrict__ bias, float* __restrict__ out, int N)
{
    constexpr bool CORR = (MODE == 1);
    constexpr int NCHAIN = CORR ? 3 : 1;
    constexpr int SA_HI = 0;
    constexpr int SA_LO = CORR ? 128 * RSTR : 0;
    constexpr int SB_HI = CORR ? 2 * 128 * RSTR : 128 * RSTR;
    constexpr int SB_LO = CORR ? 2 * 128 * RSTR + 64 * RSTR : 0;
    constexpr int STGSZ = CORR ? (2 * 128 * RSTR + 2 * 64 * RSTR) : 192 * RSTR;

    extern __shared__ char smem[];
    const uint32_t sb = smem_u32(smem);
    const int tid = threadIdx.x;
    const int lane = tid & 31;
    const int wid = tid >> 5;
    const int bm = blockIdx.y * 128;
    const int bn = blockIdx.x * 64;
    const int chunk = (MODE == 1) ? (bn >> 9) : 0;      // MODE1: 0=k 1=q

    auto issue_stage = [&](int stage, int k0) {
        const uint32_t stg = sb + stage * STGSZ;
#pragma unroll
        for (int k = 0; k < 4; ++k) {
            int idx = tid + k * 256;
            int r = idx >> 3, c = idx & 7;
            CP16(stg + SA_HI + r * RSTR + c * 16,
                 Ahi + (size_t)(bm + r) * C_ + k0 + c * 8);
            if (CORR)
                CP16(stg + SA_LO + r * RSTR + c * 16,
                     Alo + (size_t)(bm + r) * C_ + k0 + c * 8);
        }
#pragma unroll
        for (int k = 0; k < 2; ++k) {
            int idx = tid + k * 256;
            int r = idx >> 3, c = idx & 7;
            CP16(stg + SB_HI + r * RSTR + c * 16,
                 Bhi + (size_t)(k0 + r) * N + bn + c * 8);
            if (CORR)
                CP16(stg + SB_LO + r * RSTR + c * 16,
                     Blo + (size_t)(k0 + r) * N + bn + c * 8);
        }
    };
    issue_stage(0, 0);
    CP_COMMIT();

    float acc[8][4];
#pragma unroll
    for (int nb = 0; nb < 8; ++nb)
#pragma unroll
        for (int j = 0; j < 4; ++j) acc[nb][j] = 0.f;

    const int qr0 = wid * 16;
    const uint32_t a_row_off =
        (uint32_t)((qr0 + (lane & 7) + ((lane >> 3) & 1) * 8) * RSTR + (lane >> 4) * 16);

    for (int kt = 0; kt < 8; ++kt) {
        if (kt + 1 < 8) {
            issue_stage((kt + 1) & 1, (kt + 1) * 64);
            CP_COMMIT();
            CP_WAIT(1);
        } else {
            CP_WAIT(0);
        }
        __syncthreads();

        const uint32_t stg = sb + (kt & 1) * STGSZ;
#pragma unroll
        for (int chain = 0; chain < NCHAIN; ++chain) {
            const uint32_t abase = stg + (chain == 2 ? SA_LO : SA_HI) + a_row_off;
            const uint32_t bbase = stg + (chain == 1 ? SB_LO : SB_HI) + lane * RSTR;
            uint4 af[4];
#pragma unroll
            for (int kb = 0; kb < 4; ++kb)
                af[kb] = ldsm4(abase + kb * 32);
#pragma unroll
            for (int nb = 0; nb < 8; ++nb) {
#pragma unroll
                for (int kbp = 0; kbp < 2; ++kbp) {
                    uint4 bb = ldsm4t(bbase + kbp * 32 * RSTR + nb * 16);
                    mma16816(acc[nb], af[2 * kbp].x, af[2 * kbp].y,
                             af[2 * kbp].z, af[2 * kbp].w, bb.x, bb.y);
                    mma16816(acc[nb], af[2 * kbp + 1].x, af[2 * kbp + 1].y,
                             af[2 * kbp + 1].z, af[2 * kbp + 1].w, bb.z, bb.w);
                }
            }
        }
        __syncthreads();
    }

    const int row0 = bm + qr0 + (lane >> 2);
    if (MODE == 0) {
#pragma unroll
        for (int nb = 0; nb < 8; ++nb) {
            int col = bn + nb * 8 + 2 * (lane & 3);
            float2 b2 = *(const float2*)(bias + col);
            *(float2*)(out + (size_t)row0 * C_ + col) =
                make_float2(acc[nb][0] + b2.x, acc[nb][1] + b2.y);
            *(float2*)(out + (size_t)(row0 + 8) * C_ + col) =
                make_float2(acc[nb][2] + b2.x, acc[nb][3] + b2.y);
        }
    } else if (MODE == 2) {
        // v chunk: fp16 hi only
#pragma unroll
        for (int nb = 0; nb < 8; ++nb) {
            int lc = bn + nb * 8 + 2 * (lane & 3);
#pragma unroll
            for (int half_ : {0, 1}) {
                int row = row0 + half_ * 8;
                __half2 h = __floats2half2_rn(acc[nb][2 * half_],
                                              acc[nb][2 * half_ + 1]);
                *(uint32_t*)(g_vhi + (size_t)row * C_ + lc) = *(uint32_t*)&h;
            }
        }
    } else {
        __half* hiB = chunk ? g_qhi : g_khi;
        __half* loB = chunk ? g_qlo : g_klo;
        const float sc = chunk ? QSCALE : 1.f;
#pragma unroll
        for (int nb = 0; nb < 8; ++nb) {
            int lc = (bn & 511) + nb * 8 + 2 * (lane & 3);
#pragma unroll
            for (int half_ : {0, 1}) {
                int row = row0 + half_ * 8;
                float v0 = acc[nb][2 * half_] * sc;
                float v1 = acc[nb][2 * half_ + 1] * sc;
                __half2 h = __floats2half2_rn(v0, v1);
                float2 hf = __half22float2(h);
                __half2 l = __floats2half2_rn(v0 - hf.x, v1 - hf.y);
                *(uint32_t*)(hiB + (size_t)row * C_ + lc) = *(uint32_t*)&h;
                *(uint32_t*)(loB + (size_t)row * C_ + lc) = *(uint32_t*)&l;
            }
        }
    }
}

#define G_SMEM_FULL (2 * (2 * 128 * RSTR + 2 * 64 * RSTR))   // 110592
#define G_SMEM_CPT  (2 * (192 * RSTR))                        // 55296

// ============================================================================
// Attention, split-K (2 splits of 32 k-tiles). Partials -> g_po/g_pm/g_prs.
// ============================================================================
#define QHI_OFF 0
#define QLO_OFF (128 * RSTR)
#define STG_OFF (2 * 128 * RSTR)
#define TSZ (64 * RSTR)
#define KHI_SUB 0
#define KLO_SUB TSZ
#define VHI_SUB (2 * TSZ)
#define STG_SZ (3 * TSZ)                   // 27648
#define ATTN_SMEM (STG_OFF + 2 * STG_SZ)   // 92160 B

__global__ void __launch_bounds__(256) attn_mma()
{
    extern __shared__ char smem[];
    const uint32_t sb = smem_u32(smem);
    const int tid = threadIdx.x;
    const int lane = tid & 31;
    const int wid = tid >> 5;

    const int split = blockIdx.x & 1;
    const int qt = (blockIdx.x >> 1) & 31;
    const int h = (blockIdx.x >> 6) & 7;
    const int b = blockIdx.x >> 9;

    const size_t bL = (size_t)b * L_;
    const int hc = h * D_;
    const int kt0 = split * 32, kt1 = kt0 + 32;

    {
        const __half* qs[2] = {g_qhi, g_qlo};
#pragma unroll
        for (int k = 0; k < 8; ++k) {
            int idx = tid + k * 256;
            int buf = idx >> 10;
            int r = (idx >> 3) & 127;
            int c = idx & 7;
            const __half* src = qs[buf] + (bL + qt * 128 + r) * C_ + hc + c * 8;
            CP16(sb + (buf ? QLO_OFF : QHI_OFF) + r * RSTR + c * 16, src);
        }
    }
    const __half* kvsrc[3] = {g_khi, g_klo, g_vhi};
    auto issue_stage = [&](int stage, int kt) {
        const uint32_t stg = sb + STG_OFF + stage * STG_SZ;
#pragma unroll
        for (int s = 0; s < 3; ++s) {
#pragma unroll
            for (int k = 0; k < 2; ++k) {
                int idx = tid + k * 256;
                int r = idx >> 3;
                int c = idx & 7;
                const __half* src = kvsrc[s] + (bL + kt * 64 + r) * C_ + hc + c * 8;
                CP16(stg + s * TSZ + r * RSTR + c * 16, src);
            }
        }
    };
    issue_stage(kt0 & 1, kt0);
    CP_COMMIT();

    float Oc[8][4];
#pragma unroll
    for (int nb = 0; nb < 8; ++nb)
#pragma unroll
        for (int j = 0; j < 4; ++j) Oc[nb][j] = 0.f;
    float m0 = -1e30f, m1 = -1e30f, rs0 = 0.f, rs1 = 0.f;

    const int qr0 = wid * 16;
    const uint32_t q_row_off =
        (uint32_t)((qr0 + (lane & 7) + ((lane >> 3) & 1) * 8) * RSTR + (lane >> 4) * 16);

    for (int kt = kt0; kt < kt1; ++kt) {
        if (kt + 1 < kt1) {
            issue_stage((kt + 1) & 1, kt + 1);
            CP_COMMIT();
            CP_WAIT(1);
        } else {
            CP_WAIT(0);
        }
        __syncthreads();

        const uint32_t stg = sb + STG_OFF + (kt & 1) * STG_SZ;

        float Sc[8][4];
#pragma unroll
        for (int nb = 0; nb < 8; ++nb)
#pragma unroll
            for (int j = 0; j < 4; ++j) Sc[nb][j] = 0.f;

#pragma unroll
        for (int chain = 0; chain < 3; ++chain) {
            const uint32_t qbase = sb + (chain == 2 ? QLO_OFF : QHI_OFF) + q_row_off;
            const uint32_t kbase = stg + (chain == 1 ? KLO_SUB : KHI_SUB);
            uint4 qf[4];
#pragma unroll
            for (int kb = 0; kb < 4; ++kb)
                qf[kb] = ldsm4(qbase + kb * 32);
            const uint32_t krow = kbase + (uint32_t)((lane & 7) * RSTR + (lane >> 3) * 16);
#pragma unroll
            for (int nb = 0; nb < 8; ++nb) {
                const uint32_t ka = krow + nb * 8 * RSTR;
#pragma unroll
                for (int kbp = 0; kbp < 2; ++kbp) {
                    uint4 bb = ldsm4(ka + kbp * 64);
                    mma16816(Sc[nb], qf[2 * kbp].x, qf[2 * kbp].y,
                             qf[2 * kbp].z, qf[2 * kbp].w, bb.x, bb.y);
                    mma16816(Sc[nb], qf[2 * kbp + 1].x, qf[2 * kbp + 1].y,
                             qf[2 * kbp + 1].z, qf[2 * kbp + 1].w, bb.z, bb.w);
                }
            }
        }

        float t0 = -1e30f, t1 = -1e30f;
#pragma unroll
        for (int nb = 0; nb < 8; ++nb) {
            t0 = fmaxf(t0, fmaxf(Sc[nb][0], Sc[nb][1]));
            t1 = fmaxf(t1, fmaxf(Sc[nb][2], Sc[nb][3]));
        }
        t0 = fmaxf(t0, __shfl_xor_sync(0xFFFFFFFFu, t0, 1));
        t0 = fmaxf(t0, __shfl_xor_sync(0xFFFFFFFFu, t0, 2));
        t1 = fmaxf(t1, __shfl_xor_sync(0xFFFFFFFFu, t1, 1));
        t1 = fmaxf(t1, __shfl_xor_sync(0xFFFFFFFFu, t1, 2));
        const float mn0 = fmaxf(m0, t0), mn1 = fmaxf(m1, t1);
        const float corr0 = exp2_fast(m0 - mn0), corr1 = exp2_fast(m1 - mn1);
        m0 = mn0; m1 = mn1;

        uint32_t pA[4][4];
        float ps0 = 0.f, ps1 = 0.f;
#pragma unroll
        for (int nb = 0; nb < 8; ++nb) {
            float p00 = exp2_fast(Sc[nb][0] - m0);
            float p01 = exp2_fast(Sc[nb][1] - m0);
            float p10 = exp2_fast(Sc[nb][2] - m1);
            float p11 = exp2_fast(Sc[nb][3] - m1);
            __half2 hlo = __floats2half2_rn(p00, p01);
            __half2 hhi = __floats2half2_rn(p10, p11);
            float2 flo = __half22float2(hlo);
            float2 fhi = __half22float2(hhi);
            ps0 += flo.x + flo.y;
            ps1 += fhi.x + fhi.y;
            uint32_t lo2 = *reinterpret_cast<uint32_t*>(&hlo);
            uint32_t hi2 = *reinterpret_cast<uint32_t*>(&hhi);
            if (nb & 1) { pA[nb >> 1][2] = lo2; pA[nb >> 1][3] = hi2; }
            else        { pA[nb >> 1][0] = lo2; pA[nb >> 1][1] = hi2; }
        }
        ps0 += __shfl_xor_sync(0xFFFFFFFFu, ps0, 1);
        ps0 += __shfl_xor_sync(0xFFFFFFFFu, ps0, 2);
        ps1 += __shfl_xor_sync(0xFFFFFFFFu, ps1, 1);
        ps1 += __shfl_xor_sync(0xFFFFFFFFu, ps1, 2);
        rs0 = rs0 * corr0 + ps0;
        rs1 = rs1 * corr1 + ps1;
#pragma unroll
        for (int nb = 0; nb < 8; ++nb) {
            Oc[nb][0] *= corr0; Oc[nb][1] *= corr0;
            Oc[nb][2] *= corr1; Oc[nb][3] *= corr1;
        }

        // O += P Vhi
        {
            const uint32_t vbase = stg + VHI_SUB + lane * RSTR;
#pragma unroll
            for (int nb = 0; nb < 8; ++nb) {
#pragma unroll
                for (int kbp = 0; kbp < 2; ++kbp) {
                    uint4 vv = ldsm4t(vbase + kbp * 32 * RSTR + nb * 16);
                    mma16816(Oc[nb], pA[2 * kbp][0], pA[2 * kbp][1],
                             pA[2 * kbp][2], pA[2 * kbp][3], vv.x, vv.y);
                    mma16816(Oc[nb], pA[2 * kbp + 1][0], pA[2 * kbp + 1][1],
                             pA[2 * kbp + 1][2], pA[2 * kbp + 1][3], vv.z, vv.w);
                }
            }
        }
        __syncthreads();
    }

    // ---------- epilogue: store unnormalized partials ----------
    const int rowb = (b * H_ + h) * L_ + qt * 128 + qr0 + (lane >> 2);
    float* po = g_po + (size_t)split * NROWS * D_;
#pragma unroll
    for (int nb = 0; nb < 8; ++nb) {
        int c = nb * 8 + 2 * (lane & 3);
        *(float2*)(po + (size_t)rowb * D_ + c) = make_float2(Oc[nb][0], Oc[nb][1]);
        *(float2*)(po + (size_t)(rowb + 8) * D_ + c) = make_float2(Oc[nb][2], Oc[nb][3]);
    }
    if ((lane & 3) == 0) {
        g_pm[split * NROWS + rowb] = m0;
        g_prs[split * NROWS + rowb] = rs0;
        g_pm[split * NROWS + rowb + 8] = m1;
        g_prs[split * NROWS + rowb + 8] = rs1;
    }
}

// ============================================================================
// Combine: 16 threads per row (4 cols each), grid 4096 — max latency-hiding.
// ============================================================================
__global__ void __launch_bounds__(256) combine_kernel()
{
    const int gid = blockIdx.x * blockDim.x + threadIdx.x;
    const int row = gid >> 4;
    const int c0 = (gid & 15) * 4;

    const float m0 = g_pm[row], m1 = g_pm[NROWS + row];
    const float rs0 = g_prs[row], rs1 = g_prs[NROWS + row];
    const float m = fmaxf(m0, m1);
    float a0 = exp2_fast(m0 - m), a1 = exp2_fast(m1 - m);
    const float inv = 1.f / (a0 * rs0 + a1 * rs1);
    a0 *= inv; a1 *= inv;

    const int b = row >> 15;
    const int h = (row >> 12) & 7;
    const int l = row & (L_ - 1);
    const size_t obase = ((size_t)(b * L_ + l)) * C_ + h * D_ + c0;
    const float* p0 = g_po + (size_t)row * D_ + c0;
    const float* p1 = g_po + (size_t)NROWS * D_ + (size_t)row * D_ + c0;

    float4 v0 = *(const float4*)p0;
    float4 v1 = *(const float4*)p1;
    __half2 h01 = __floats2half2_rn(a0 * v0.x + a1 * v1.x,
                                    a0 * v0.y + a1 * v1.y);
    __half2 h23 = __floats2half2_rn(a0 * v0.z + a1 * v1.z,
                                    a0 * v0.w + a1 * v1.w);
    *(uint2*)(g_ahi + obase) = make_uint2(*(uint32_t*)&h01, *(uint32_t*)&h23);
}

// ============================================================================
// Launch
// ============================================================================
extern "C" void kernel_launch(void* const* d_in, const int* in_sizes, int n_in,
                              void* d_out, int out_size)
{
    const float* x     = (const float*)d_in[0];
    const float* w_kqv = (const float*)d_in[1];
    const float* w_out = (const float*)d_in[2];
    const float* b_out = (const float*)d_in[3];
    float* out = (float*)d_out;

    __half *xhi, *xlo, *wkhi, *wklo, *wohi, *ahi;
    cudaGetSymbolAddress((void**)&xhi, g_xhi);
    cudaGetSymbolAddress((void**)&xlo, g_xlo);
    cudaGetSymbolAddress((void**)&wkhi, g_wkhi);
    cudaGetSymbolAddress((void**)&wklo, g_wklo);
    cudaGetSymbolAddress((void**)&wohi, g_wohi);
    cudaGetSymbolAddress((void**)&ahi, g_ahi);

    cudaFuncSetAttribute(attn_mma,
                         cudaFuncAttributeMaxDynamicSharedMemorySize, ATTN_SMEM);
    cudaFuncSetAttribute(hgemm<0>,
                         cudaFuncAttributeMaxDynamicSharedMemorySize, G_SMEM_CPT);
    cudaFuncSetAttribute(hgemm<1>,
                         cudaFuncAttributeMaxDynamicSharedMemorySize, G_SMEM_FULL);
    cudaFuncSetAttribute(hgemm<2>,
                         cudaFuncAttributeMaxDynamicSharedMemorySize, G_SMEM_CPT);

    // 0) fused fp32 -> fp16 hi/lo splits
    split_all<<<1536, 256>>>((const float4*)x, (const float4*)w_kqv,
                             (const float4*)w_out);

    // 1a) k/q projection (3 chains, unrolled)
    hgemm<1><<<dim3(16, ROWS_ / 128), 256, G_SMEM_FULL>>>(
        xhi, xlo, wkhi, wklo, nullptr, nullptr, THREE_C);

    // 1b) v projection (1 chain, compact smem)
    hgemm<2><<<dim3(8, ROWS_ / 128), 256, G_SMEM_CPT>>>(
        xhi, nullptr, wkhi + 1024, nullptr, nullptr, nullptr, THREE_C);

    // 2) attention split-K partials (grid 1024)
    attn_mma<<<B_ * H_ * (L_ / 128) * NSPLIT, 256, ATTN_SMEM>>>();

    // 2b) combine partials -> g_ahi
    combine_kernel<<<4096, 256>>>();

    // 3) out = attn @ w_out + bias (single-chain HMMA, compact smem)
    hgemm<0><<<dim3(C_ / 64, ROWS_ / 128), 256, G_SMEM_CPT>>>(
        ahi, nullptr, wohi, nullptr, b_out, out, C_);
}